// round 15
// baseline (speedup 1.0000x reference)
#include <cuda_runtime.h>
#include <cuda_fp16.h>
#include <math.h>
#include <stdint.h>

#define NB 8
#define NN 2000
#define NH 64
#define NPAD 2048
#define VC 144   // vT rows: 128 cols of [h|h2] + ones col + pad

// ---------------- scratch ----------------
__device__ float  d_h   [NB*NN*NH];
__device__ float  d_e1  [NB*NN];
__device__ float  d_e2  [NB*NN];
__device__ __half d_Ah  [(size_t)NPAD*NPAD];
__device__ __half d_vsh [(size_t)NPAD*NPAD];
__device__ __half d_sigT[(size_t)NB*NPAD*NPAD];
__device__ __half d_expT[(size_t)NB*NPAD*NPAD];
__device__ __half d_vT  [(size_t)NB*VC*NPAD];
__device__ float  d_rs  [NB*NN];
__device__ __half d_wallh[(size_t)NN*8192];    // per-node adaptive weights, fp16
__device__ float  d_xg  [(size_t)NB*NN*128];
__device__ __half d_gh  [NB*NN*NH];
__device__ __half d_Woh [4096*64];

// ---------------- helpers ----------------
__device__ __forceinline__ void mma16816(float* d,
    uint32_t a0, uint32_t a1, uint32_t a2, uint32_t a3, uint32_t b0, uint32_t b1) {
  asm volatile(
    "mma.sync.aligned.m16n8k16.row.col.f32.f16.f16.f32 "
    "{%0,%1,%2,%3},{%4,%5,%6,%7},{%8,%9},{%0,%1,%2,%3};"
    : "+f"(d[0]), "+f"(d[1]), "+f"(d[2]), "+f"(d[3])
    : "r"(a0), "r"(a1), "r"(a2), "r"(a3), "r"(b0), "r"(b1));
}
__device__ __forceinline__ uint32_t smem_u32(const void* p) {
  uint32_t a;
  asm("{ .reg .u64 t; cvta.to.shared.u64 t, %1; cvt.u32.u64 %0, t; }" : "=r"(a) : "l"(p));
  return a;
}
__device__ __forceinline__ void ldsm4(uint32_t& r0, uint32_t& r1, uint32_t& r2, uint32_t& r3,
                                      uint32_t addr) {
  asm volatile("ldmatrix.sync.aligned.m8n8.x4.shared.b16 {%0,%1,%2,%3}, [%4];"
    : "=r"(r0), "=r"(r1), "=r"(r2), "=r"(r3) : "r"(addr));
}
__device__ __forceinline__ void cpa16(uint32_t saddr, const void* g) {
  asm volatile("cp.async.cg.shared.global [%0], [%1], 16;" :: "r"(saddr), "l"(g));
}
#define CPA_COMMIT() asm volatile("cp.async.commit_group;" ::: "memory")
#define CPA_WAIT(n)  asm volatile("cp.async.wait_group %0;" :: "n"(n) : "memory")

// ---------------- K1: h, e1, e2 ----------------
__global__ __launch_bounds__(256) void k1_h(const float* __restrict__ z,
    const float* __restrict__ W_in, const float* __restrict__ b_in,
    const float* __restrict__ w1, const float* __restrict__ w2) {
  int t = threadIdx.x;
  int sub = t >> 6;
  int j = t & 63;
  int bn = blockIdx.x * 4 + sub;
  __shared__ float W_s[64][65];
  __shared__ float zs[4][64];
  __shared__ float r1[4][64], r2[4][64];
  #pragma unroll
  for (int u = 0; u < 16; ++u) {
    int idx = t + 256*u;
    W_s[idx >> 6][idx & 63] = W_in[idx];
  }
  zs[sub][j] = z[bn*64 + j];
  __syncthreads();
  float acc = b_in[j];
  #pragma unroll
  for (int c = 0; c < 64; ++c) acc = fmaf(zs[sub][c], W_s[j][c], acc);
  float hv = fmaxf(acc, 0.0f);
  d_h[bn*64 + j] = hv;
  r1[sub][j] = hv * w1[j];
  r2[sub][j] = hv * w2[j];
  __syncthreads();
  if (j < 32) {
    float s1 = r1[sub][j] + r1[sub][j+32];
    float s2 = r2[sub][j] + r2[sub][j+32];
    #pragma unroll
    for (int o = 16; o > 0; o >>= 1) {
      s1 += __shfl_down_sync(0xffffffffu, s1, o);
      s2 += __shfl_down_sync(0xffffffffu, s2, o);
    }
    if (j == 0) { d_e1[bn] = s1; d_e2[bn] = s2; }
  }
}

// ---------------- K2: Ah = fp16 rowsoftmax(relu(emb emb^T)), padded ----------------
__global__ __launch_bounds__(256) void k2_A(const float* __restrict__ emb) {
  int n = blockIdx.x;
  int t = threadIdx.x;
  __shared__ float row[NN];
  __shared__ float e_n[16];
  __shared__ float red[256];
  if (t < 16) e_n[t] = emb[n*16 + t];
  __syncthreads();
  float lmax = -3e38f;
  for (int m = t; m < NN; m += 256) {
    const float* em = emb + m*16;
    float s = 0.f;
    #pragma unroll
    for (int d = 0; d < 16; ++d) s = fmaf(e_n[d], em[d], s);
    s = fmaxf(s, 0.f);
    row[m] = s;
    lmax = fmaxf(lmax, s);
  }
  red[t] = lmax; __syncthreads();
  for (int o = 128; o > 0; o >>= 1) {
    if (t < o) red[t] = fmaxf(red[t], red[t+o]);
    __syncthreads();
  }
  float mx = red[0];
  __syncthreads();
  float lsum = 0.f;
  for (int m = t; m < NN; m += 256) {
    float e = __expf(row[m] - mx);
    row[m] = e;
    lsum += e;
  }
  red[t] = lsum; __syncthreads();
  for (int o = 128; o > 0; o >>= 1) {
    if (t < o) red[t] += red[t+o];
    __syncthreads();
  }
  float inv = 1.0f / red[0];
  __syncthreads();
  for (int m = t; m < NN; m += 256) d_Ah[(size_t)n*NPAD + m] = __float2half(row[m] * inv);
  if (t < NPAD - NN) d_Ah[(size_t)n*NPAD + NN + t] = __float2half(0.f);
}

// ---------------- kv_pack_h: vT rows 0..63 = h^T, coalesced transpose ----------------
__global__ __launch_bounds__(256) void kv_pack_h() {
  int b  = blockIdx.y;
  int p0 = blockIdx.x * 128;
  int t = threadIdx.x;
  __shared__ float s[128][65];
  const float* Hb = d_h + (size_t)b*NN*64;
  #pragma unroll
  for (int u = 0; u < 32; ++u) {
    int idx = t + 256*u;
    int row = idx >> 6, col = idx & 63;
    int p = p0 + row;
    s[row][col] = (p < NN) ? Hb[(size_t)p*64 + col] : 0.f;
  }
  __syncthreads();
  __half* dst = d_vT + (size_t)b*VC*NPAD;
  #pragma unroll
  for (int u = 0; u < 16; ++u) {
    int idx = t + 256*u;
    int c = idx >> 6, q = idx & 63;
    int pl = q*2;
    __half2 v = __floats2half2_rn(s[pl][c], s[pl+1][c]);
    *(__half2*)(dst + (size_t)c*NPAD + p0 + pl) = v;
  }
}

// ---------------- kv_ones: vT row 128 = 1, rows 129..143 = 0 ----------------
__global__ __launch_bounds__(256) void kv_ones() {
  int b = blockIdx.x;
  int t = threadIdx.x;
  __half one = __float2half(1.f), zero = __float2half(0.f);
  __half* base = d_vT + (size_t)b*VC*NPAD;
  #pragma unroll
  for (int u = 0; u < 8; ++u) base[(size_t)128*NPAD + t + 256*u] = one;
  for (int c = 129; c < VC; ++c)
    #pragma unroll
    for (int u = 0; u < 8; ++u) base[(size_t)c*NPAD + t + 256*u] = zero;
}

// ---------------- K3: h2 = A @ h -> vT rows 64..127 ----------------
__global__ __launch_bounds__(256) void k3_mma() {
  int b  = blockIdx.y;
  int i0 = blockIdx.x * 128;
  int t = threadIdx.x;
  int w = t >> 5, lane = t & 31;
  int wm = w & 3, wn = w >> 2;
  int gid = lane >> 2, tid2 = lane & 3;

  __shared__ __half As[128*72];
  __shared__ __half Bs[64*72];

  const __half* Ag = d_Ah + (size_t)i0*NPAD;
  const __half* Bg = d_vT + (size_t)b*VC*NPAD;

  float acc[2][4][4];
  #pragma unroll
  for (int am = 0; am < 2; ++am)
    #pragma unroll
    for (int bn = 0; bn < 4; ++bn)
      #pragma unroll
      for (int r = 0; r < 4; ++r) acc[am][bn][r] = 0.f;

  #pragma unroll 1
  for (int k0 = 0; k0 < NPAD; k0 += 64) {
    __syncthreads();
    #pragma unroll
    for (int u = 0; u < 4; ++u) {
      int lin = t + 256*u;
      int row = lin >> 3, q = lin & 7;
      *(float4*)&As[row*72 + q*8] = *(const float4*)(Ag + (size_t)row*NPAD + k0 + q*8);
    }
    #pragma unroll
    for (int u = 0; u < 2; ++u) {
      int lin = t + 256*u;
      int row = lin >> 3, q = lin & 7;
      *(float4*)&Bs[row*72 + q*8] = *(const float4*)(Bg + (size_t)row*NPAD + k0 + q*8);
    }
    __syncthreads();
    #pragma unroll
    for (int kk = 0; kk < 4; ++kk) {
      int kb = kk*16;
      uint32_t a[2][4], bf[4][2];
      #pragma unroll
      for (int am = 0; am < 2; ++am) {
        int r0 = wm*32 + am*16 + gid;
        a[am][0] = *(const uint32_t*)&As[ r0      *72 + kb + tid2*2];
        a[am][1] = *(const uint32_t*)&As[(r0 + 8) *72 + kb + tid2*2];
        a[am][2] = *(const uint32_t*)&As[ r0      *72 + kb + tid2*2 + 8];
        a[am][3] = *(const uint32_t*)&As[(r0 + 8) *72 + kb + tid2*2 + 8];
      }
      #pragma unroll
      for (int bn = 0; bn < 4; ++bn) {
        int c0 = wn*32 + bn*8 + gid;
        bf[bn][0] = *(const uint32_t*)&Bs[c0*72 + kb + tid2*2];
        bf[bn][1] = *(const uint32_t*)&Bs[c0*72 + kb + tid2*2 + 8];
      }
      #pragma unroll
      for (int am = 0; am < 2; ++am)
        #pragma unroll
        for (int bn = 0; bn < 4; ++bn)
          mma16816(acc[am][bn], a[am][0], a[am][1], a[am][2], a[am][3], bf[bn][0], bf[bn][1]);
    }
  }

  __half* dst = d_vT + (size_t)b*VC*NPAD;
  int ib = i0 + wm*32 + gid;
  int cb = wn*32 + tid2*2;
  #pragma unroll
  for (int am = 0; am < 2; ++am) {
    #pragma unroll
    for (int bn = 0; bn < 4; ++bn) {
      int c = cb + bn*8;
      int i = ib + am*16;
      if (i < NN) {
        dst[(size_t)(64 + c    )*NPAD + i] = __float2half(acc[am][bn][0]);
        dst[(size_t)(64 + c + 1)*NPAD + i] = __float2half(acc[am][bn][1]);
      }
      if (i + 8 < NN) {
        dst[(size_t)(64 + c    )*NPAD + i + 8] = __float2half(acc[am][bn][2]);
        dst[(size_t)(64 + c + 1)*NPAD + i + 8] = __float2half(acc[am][bn][3]);
      }
    }
  }
}

// ---------------- kvs: vs -> fp16 padded ----------------
__global__ __launch_bounds__(256) void kvs_conv(const float* __restrict__ vs) {
  int idx = blockIdx.x * 256 + threadIdx.x;
  int row = idx >> 10, q = idx & 1023;
  int c0 = q * 2;
  float a = (row < NN && c0     < NN) ? vs[row*NN + c0]     : 0.f;
  float b = (row < NN && c0 + 1 < NN) ? vs[row*NN + c0 + 1] : 0.f;
  *(__half2*)(d_vsh + (size_t)row*NPAD + c0) = __floats2half2_rn(a, b);
}

// ---------------- kwo: W_out -> fp16 ----------------
__global__ __launch_bounds__(256) void kwo_conv(const float* __restrict__ W_out) {
  int idx = blockIdx.x * 256 + threadIdx.x;
  d_Woh[idx] = __float2half(W_out[idx]);
}

// ---------------- K4: sigT fp16 via h2exp/h2rcp ----------------
__global__ __launch_bounds__(256) void k4_sigT(const float* __restrict__ bs) {
  int b  = blockIdx.z;
  int m0 = blockIdx.y * 64;
  int p0 = blockIdx.x * 64;
  int t = threadIdx.x;
  __shared__ float s[64][65];
  #pragma unroll
  for (int u = 0; u < 16; ++u) {
    int idx = t + 256*u;
    int ml = idx >> 6, pl = idx & 63;
    int m = m0 + ml, p = p0 + pl;
    float x = 0.f;
    if (m < NN && p < NN)
      x = fmaf(d_e1[b*NN + m], d_e2[b*NN + p], bs[m*NN + p]);
    s[ml][pl] = fminf(fmaxf(x, -10.f), 10.f);
  }
  __syncthreads();
  __half* dst = d_sigT + (size_t)b*NPAD*NPAD;
  __half2 one2 = __float2half2_rn(1.f);
  #pragma unroll
  for (int u = 0; u < 8; ++u) {
    int idx = t + 256*u;
    int pl = idx >> 5, m2 = idx & 31;
    __half2 hx = __floats2half2_rn(s[m2*2][pl], s[m2*2+1][pl]);
    __half2 sig = h2rcp(__hadd2(one2, h2exp(__hneg2(hx))));
    *(__half2*)(dst + (size_t)(p0+pl)*NPAD + m0 + m2*2) = sig;
  }
}

// ---------------- K5a: expT = exp(vs @ sig) -- 128x128 tile, 2 CTAs/SM, ldmatrix frags ----------------
// 8 warps (2 m x 4 n), warp 64x32, BK=64, 2-stage cp.async, 73.7KB smem, 1 barrier/iter.
__global__ __launch_bounds__(256, 2) void k5a_mma() {
  extern __shared__ __half dsm[];
  int b  = blockIdx.z;
  int i0 = blockIdx.y * 128;
  int j0 = blockIdx.x * 128;
  int t = threadIdx.x;
  int w = t >> 5, lane = t & 31;
  int wm = w & 1, wn = w >> 1;
  int gid = lane >> 2, tid2 = lane & 3;

  const int BUF = 256*72;                    // halves per stage (A 128x72 + B 128x72)
  uint32_t sbase = smem_u32(dsm);

  const __half* Ag = d_vsh  + (size_t)i0 * NPAD;
  const __half* Bg = d_sigT + ((size_t)b * NPAD + j0) * NPAD;

  auto issue = [&](int buf, int k0) {
    uint32_t ab = sbase + (uint32_t)buf*BUF*2u;
    uint32_t bb = ab + 128u*72u*2u;
    #pragma unroll
    for (int u = 0; u < 4; ++u) {
      int lin = t + 256*u;
      int row = lin >> 3, q = lin & 7;
      cpa16(ab + (uint32_t)(row*72 + q*8)*2u, Ag + (size_t)row*NPAD + k0 + q*8);
      cpa16(bb + (uint32_t)(row*72 + q*8)*2u, Bg + (size_t)row*NPAD + k0 + q*8);
    }
    CPA_COMMIT();
  };

  float acc[4][4][4];
  #pragma unroll
  for (int am = 0; am < 4; ++am)
    #pragma unroll
    for (int bn = 0; bn < 4; ++bn)
      #pragma unroll
      for (int r = 0; r < 4; ++r) acc[am][bn][r] = 0.f;

  issue(0, 0);

  #pragma unroll 1
  for (int kt = 0; kt < NPAD/64; ++kt) {
    int cur = kt & 1;
    CPA_WAIT(0);
    __syncthreads();
    if (kt + 1 < NPAD/64) issue(cur ^ 1, (kt + 1)*64);
    const __half* Asc = dsm + cur*BUF;
    const __half* Bsc = Asc + 128*72;
    #pragma unroll
    for (int kk = 0; kk < 4; ++kk) {
      int kb = kk*16;
      uint32_t a[4][4];
      #pragma unroll
      for (int am = 0; am < 4; ++am) {
        int r0 = wm*64 + am*16 + (lane & 15);
        uint32_t addr = smem_u32(&Asc[r0*72 + kb + (lane >> 4)*8]);
        ldsm4(a[am][0], a[am][1], a[am][2], a[am][3], addr);
      }
      #pragma unroll
      for (int bp = 0; bp < 2; ++bp) {
        uint32_t bf0, bf1, bf2, bf3;
        int c0 = wn*32 + bp*16 + (lane & 15);
        uint32_t addr = smem_u32(&Bsc[c0*72 + kb + (lane >> 4)*8]);
        ldsm4(bf0, bf1, bf2, bf3, addr);
        #pragma unroll
        for (int am = 0; am < 4; ++am) {
          mma16816(acc[am][bp*2+0], a[am][0], a[am][1], a[am][2], a[am][3], bf0, bf2);
          mma16816(acc[am][bp*2+1], a[am][0], a[am][1], a[am][2], a[am][3], bf1, bf3);
        }
      }
    }
  }

  // epilogue: exp(fp16) -> smem staging [128][136] -> coalesced write
  __syncthreads();
  __half* sH = dsm;
  const int SST = 136;
  #pragma unroll
  for (int am = 0; am < 4; ++am) {
    #pragma unroll
    for (int bn = 0; bn < 4; ++bn) {
      int lr = wm*64 + am*16 + gid;
      int lc = wn*32 + bn*8 + tid2*2;
      __half2 t0 = __floats2half2_rn(fminf(acc[am][bn][0], 11.f), fminf(acc[am][bn][1], 11.f));
      __half2 t1 = __floats2half2_rn(fminf(acc[am][bn][2], 11.f), fminf(acc[am][bn][3], 11.f));
      *(__half2*)&sH[ lr      *SST + lc] = h2exp(t0);
      *(__half2*)&sH[(lr + 8) *SST + lc] = h2exp(t1);
    }
  }
  __syncthreads();
  __half2 zz = __floats2half2_rn(0.f, 0.f);
  #pragma unroll
  for (int u = 0; u < 32; ++u) {
    int idx = t + 256*u;                 // 128 rows x 64 half2
    int row = idx >> 6, q = idx & 63;
    int i = i0 + row, j = j0 + q*2;
    if (i < NN) {
      __half2 v = (j < NN) ? *(__half2*)&sH[row*SST + q*2] : zz;
      *(__half2*)(d_expT + ((size_t)b*NPAD + i)*NPAD + j) = v;
    }
  }
}

// ---------------- K5b: xg_raw = expT @ vT^T ----------------
__global__ __launch_bounds__(256) void k5b_mma() {
  int b  = blockIdx.y;
  int i0 = blockIdx.x * 64;
  int t = threadIdx.x;
  int w = t >> 5, lane = t & 31;
  int wm = w & 3, wn = w >> 2;
  int gid = lane >> 2, tid2 = lane & 3;

  __shared__ __half As[64*72];
  __shared__ __half Bs[VC*72];

  const __half* Ag = d_expT + ((size_t)b*NPAD + i0)*NPAD;
  const __half* Bg = d_vT + (size_t)b*VC*NPAD;

  float acc[9][4];
  #pragma unroll
  for (int bn = 0; bn < 9; ++bn)
    #pragma unroll
    for (int r = 0; r < 4; ++r) acc[bn][r] = 0.f;

  #pragma unroll 1
  for (int k0 = 0; k0 < NPAD; k0 += 64) {
    __syncthreads();
    #pragma unroll
    for (int u = 0; u < 2; ++u) {
      int lin = t + 256*u;
      int row = lin >> 3, q = lin & 7;
      *(float4*)&As[row*72 + q*8] = *(const float4*)(Ag + (size_t)row*NPAD + k0 + q*8);
    }
    #pragma unroll
    for (int u = 0; u < 5; ++u) {
      int lin = t + 256*u;
      if (lin < VC*8) {
        int row = lin >> 3, q = lin & 7;
        *(float4*)&Bs[row*72 + q*8] = *(const float4*)(Bg + (size_t)row*NPAD + k0 + q*8);
      }
    }
    __syncthreads();
    #pragma unroll
    for (int kk = 0; kk < 4; ++kk) {
      int kb = kk*16;
      int r0 = wm*16 + gid;
      uint32_t a0 = *(const uint32_t*)&As[ r0      *72 + kb + tid2*2];
      uint32_t a1 = *(const uint32_t*)&As[(r0 + 8) *72 + kb + tid2*2];
      uint32_t a2 = *(const uint32_t*)&As[ r0      *72 + kb + tid2*2 + 8];
      uint32_t a3 = *(const uint32_t*)&As[(r0 + 8) *72 + kb + tid2*2 + 8];
      #pragma unroll
      for (int bn = 0; bn < 9; ++bn) {
        int c0 = wn*72 + bn*8 + gid;
        uint32_t bf0 = *(const uint32_t*)&Bs[c0*72 + kb + tid2*2];
        uint32_t bf1 = *(const uint32_t*)&Bs[c0*72 + kb + tid2*2 + 8];
        mma16816(acc[bn], a0, a1, a2, a3, bf0, bf1);
      }
    }
  }

  int i = i0 + wm*16 + gid;
  #pragma unroll
  for (int bn = 0; bn < 9; ++bn) {
    int c = wn*72 + bn*8 + tid2*2;
    if (c < 128) {
      if (i < NN)
        *(float2*)&d_xg[((size_t)b*NN + i)*128 + c]     = make_float2(acc[bn][0], acc[bn][1]);
      if (i + 8 < NN)
        *(float2*)&d_xg[((size_t)b*NN + i + 8)*128 + c] = make_float2(acc[bn][2], acc[bn][3]);
    } else if (c == 128) {
      if (i < NN)     d_rs[b*NN + i]     = acc[bn][0];
      if (i + 8 < NN) d_rs[b*NN + i + 8] = acc[bn][2];
    }
  }
}

// ---------------- kw: w_allh = emb @ wp (fp16 out) ----------------
__global__ __launch_bounds__(256) void kw(const float* __restrict__ emb,
                                          const float* __restrict__ wp) {
  int c0 = blockIdx.x * 512;
  int n0 = blockIdx.y * 32;
  int t = threadIdx.x;
  __shared__ float wp_s[16][512];
  __shared__ float e_s[32][17];
  #pragma unroll
  for (int u = 0; u < 32; ++u) {
    int idx = t + 256*u;
    int d = idx >> 9, col = idx & 511;
    wp_s[d][col] = wp[d*8192 + c0 + col];
  }
  #pragma unroll
  for (int u = 0; u < 2; ++u) {
    int idx = t + 256*u;
    int nl = idx >> 4, d = idx & 15;
    e_s[nl][d] = (n0 + nl < NN) ? emb[(n0+nl)*16 + d] : 0.f;
  }
  __syncthreads();
  #pragma unroll 4
  for (int u = 0; u < 32; ++u) {
    int idx = t + 256*u;
    int nl = idx >> 8, cp = idx & 255;
    int col = cp*2;
    float a0 = 0.f, a1 = 0.f;
    #pragma unroll
    for (int d = 0; d < 16; ++d) {
      float e = e_s[nl][d];
      a0 = fmaf(e, wp_s[d][col],     a0);
      a1 = fmaf(e, wp_s[d][col + 1], a1);
    }
    if (n0 + nl < NN)
      *(__half2*)&d_wallh[(size_t)(n0+nl)*8192 + c0 + col] = __floats2half2_rn(a0, a1);
  }
}

// ---------------- K6: g(fp16) = bias + (xg_raw @ w_all[n]) / rowsum ----------------
__global__ __launch_bounds__(256) void k6_g(const float* __restrict__ emb,
                                            const float* __restrict__ bp) {
  int n = blockIdx.x;
  int t = threadIdx.x;
  __shared__ float w_s[8192];
  __shared__ float e_s[16];
  __shared__ float bias_s[64];
  __shared__ float xg_s[8][128];
  __shared__ float inv_s[8];
  if (t < 16) e_s[t] = emb[n*16 + t];
  if (t >= 32 && t < 40) inv_s[t-32] = 1.0f / d_rs[(t-32)*NN + n];
  __syncthreads();
  #pragma unroll 4
  for (int u = 0; u < 16; ++u) {
    int idx = t + 256*u;
    __half2 hv = *(const __half2*)&d_wallh[(size_t)n*8192 + idx*2];
    float2 fv = __half22float2(hv);
    w_s[idx*2]     = fv.x;
    w_s[idx*2 + 1] = fv.y;
  }
  if (t < 64) {
    float acc = 0.f;
    #pragma unroll
    for (int d = 0; d < 16; ++d) acc = fmaf(e_s[d], bp[d*64 + t], acc);
    bias_s[t] = acc;
  }
  #pragma unroll
  for (int u = 0; u < 4; ++u) {
    int idx = t + 256*u;
    int b = idx >> 7, ki = idx & 127;
    xg_s[b][ki] = d_xg[((size_t)b*NN + n)*128 + ki];
  }
  __syncthreads();
  #pragma unroll
  for (int u = 0; u < 2; ++u) {
    int idx = t + 256*u;
    int b = idx >> 6, o = idx & 63;
    float acc = 0.f;
    #pragma unroll 8
    for (int ki = 0; ki < 128; ++ki) acc = fmaf(xg_s[b][ki], w_s[ki*64 + o], acc);
    d_gh[(b*NN + n)*64 + o] = __float2half(fmaf(acc, inv_s[b], bias_s[o]));
  }
}

// ---------------- K7: out = 0.1*tanh(g @ W_out^T + b_out) via HMMA, K=64 ----------------
__global__ __launch_bounds__(256) void k7_mma(const float* __restrict__ b_out,
                                              float* __restrict__ out) {
  int o0 = blockIdx.x * 128;
  int r0g = blockIdx.y * 128;
  int t = threadIdx.x;
  int w = t >> 5, lane = t & 31;
  int wm = w & 1, wn = w >> 1;
  int gid = lane >> 2, tid2 = lane & 3;

  __shared__ __half As[128*72];
  __shared__ __half Bs[128*72];

  #pragma unroll
  for (int u = 0; u < 4; ++u) {
    int lin = t + 256*u;
    int row = lin >> 3, q = lin & 7;
    *(float4*)&As[row*72 + q*8] = *(const float4*)(d_gh  + (size_t)(r0g + row)*64 + q*8);
    *(float4*)&Bs[row*72 + q*8] = *(const float4*)(d_Woh + (size_t)(o0  + row)*64 + q*8);
  }
  __syncthreads();

  float acc[4][4][4];
  #pragma unroll
  for (int am = 0; am < 4; ++am)
    #pragma unroll
    for (int bn = 0; bn < 4; ++bn)
      #pragma unroll
      for (int r = 0; r < 4; ++r) acc[am][bn][r] = 0.f;

  #pragma unroll
  for (int kk = 0; kk < 4; ++kk) {
    int kb = kk*16;
    uint32_t a[4][4];
    #pragma unroll
    for (int am = 0; am < 4; ++am) {
      int r0 = wm*64 + am*16 + gid;
      a[am][0] = *(const uint32_t*)&As[ r0      *72 + kb + tid2*2];
      a[am][1] = *(const uint32_t*)&As[(r0 + 8) *72 + kb + tid2*2];
      a[am][2] = *(const uint32_t*)&As[ r0      *72 + kb + tid2*2 + 8];
      a[am][3] = *(const uint32_t*)&As[(r0 + 8) *72 + kb + tid2*2 + 8];
    }
    #pragma unroll
    for (int bn = 0; bn < 4; ++bn) {
      int c0 = wn*32 + bn*8 + gid;
      uint32_t bf0 = *(const uint32_t*)&Bs[c0*72 + kb + tid2*2];
      uint32_t bf1 = *(const uint32_t*)&Bs[c0*72 + kb + tid2*2 + 8];
      #pragma unroll
      for (int am = 0; am < 4; ++am)
        mma16816(acc[am][bn], a[am][0], a[am][1], a[am][2], a[am][3], bf0, bf1);
    }
  }

  #pragma unroll
  for (int bn = 0; bn < 4; ++bn) {
    int j = o0 + wn*32 + bn*8 + tid2*2;
    float2 bo = *(const float2*)&b_out[j];
    #pragma unroll
    for (int am = 0; am < 4; ++am) {
      int i = r0g + wm*64 + am*16 + gid;
      float2 v0, v1;
      v0.x = 0.1f * tanhf(acc[am][bn][0] + bo.x);
      v0.y = 0.1f * tanhf(acc[am][bn][1] + bo.y);
      v1.x = 0.1f * tanhf(acc[am][bn][2] + bo.x);
      v1.y = 0.1f * tanhf(acc[am][bn][3] + bo.y);
      *(float2*)&out[(size_t)i*4096 + j]       = v0;
      *(float2*)&out[(size_t)(i+8)*4096 + j]   = v1;
    }
  }
}

// ---------------- launch ----------------
extern "C" void kernel_launch(void* const* d_in, const int* in_sizes, int n_in,
                              void* d_out, int out_size) {
  const float* z     = (const float*)d_in[0];
  const float* W_in  = (const float*)d_in[1];
  const float* b_in  = (const float*)d_in[2];
  const float* W_out = (const float*)d_in[3];
  const float* b_out = (const float*)d_in[4];
  const float* emb   = (const float*)d_in[5];
  const float* wp    = (const float*)d_in[6];
  const float* bp    = (const float*)d_in[7];
  const float* w1    = (const float*)d_in[8];
  const float* w2    = (const float*)d_in[9];
  const float* vs    = (const float*)d_in[10];
  const float* bs    = (const float*)d_in[11];
  float* out = (float*)d_out;

  static bool attr_set = false;
  if (!attr_set) {
    cudaFuncSetAttribute(k5a_mma, cudaFuncAttributeMaxDynamicSharedMemorySize, 73728);
    attr_set = true;
  }

  // k5a_mma kept as 4th launch so the ncu window captures it.
  k1_h<<<4000, 256>>>(z, W_in, b_in, w1, w2);
  kvs_conv<<<8192, 256>>>(vs);
  k4_sigT<<<dim3(32, 32, NB), 256>>>(bs);
  k5a_mma<<<dim3(16, 16, NB), 256, 73728>>>();
  k2_A<<<NN, 256>>>(emb);
  kwo_conv<<<1024, 256>>>(W_out);
  kv_pack_h<<<dim3(16, NB), 256>>>();
  kv_ones<<<NB, 256>>>();
  k3_mma<<<dim3(16, NB), 256>>>();
  k5b_mma<<<dim3(32, NB), 256>>>();
  kw<<<dim3(16, 63), 256>>>(emb, wp);
  k6_g<<<NN, 256>>>(emb, bp);
  k7_mma<<<dim3(32, 125), 256>>>(b_out, out);
}

// round 16
// speedup vs baseline: 1.0511x; 1.0511x over previous
#include <cuda_runtime.h>
#include <cuda_fp16.h>
#include <math.h>
#include <stdint.h>

#define NB 8
#define NN 2000
#define NH 64
#define NPAD 2048
#define VC 144   // vT rows: 128 cols of [h|h2] + ones col + pad

// ---------------- scratch ----------------
__device__ float  d_h   [NB*NN*NH];
__device__ float  d_e1  [NB*NN];
__device__ float  d_e2  [NB*NN];
__device__ __half d_Ah  [(size_t)NPAD*NPAD];
__device__ __half d_vsh [(size_t)NPAD*NPAD];
__device__ __half d_sigT[(size_t)NB*NPAD*NPAD];
__device__ __half d_expT[(size_t)NB*NPAD*NPAD];
__device__ __half d_vT  [(size_t)NB*VC*NPAD];
__device__ float  d_rs  [NB*NN];
__device__ __half d_wallh[(size_t)NN*8192];    // per-node adaptive weights, fp16
__device__ float  d_xg  [(size_t)NB*NN*128];
__device__ __half d_gh  [NB*NN*NH];
__device__ __half d_Woh [4096*64];

// ---------------- helpers ----------------
__device__ __forceinline__ void mma16816(float* d,
    uint32_t a0, uint32_t a1, uint32_t a2, uint32_t a3, uint32_t b0, uint32_t b1) {
  asm volatile(
    "mma.sync.aligned.m16n8k16.row.col.f32.f16.f16.f32 "
    "{%0,%1,%2,%3},{%4,%5,%6,%7},{%8,%9},{%0,%1,%2,%3};"
    : "+f"(d[0]), "+f"(d[1]), "+f"(d[2]), "+f"(d[3])
    : "r"(a0), "r"(a1), "r"(a2), "r"(a3), "r"(b0), "r"(b1));
}
__device__ __forceinline__ uint32_t smem_u32(const void* p) {
  uint32_t a;
  asm("{ .reg .u64 t; cvta.to.shared.u64 t, %1; cvt.u32.u64 %0, t; }" : "=r"(a) : "l"(p));
  return a;
}
__device__ __forceinline__ void cpa16(uint32_t saddr, const void* g) {
  asm volatile("cp.async.cg.shared.global [%0], [%1], 16;" :: "r"(saddr), "l"(g));
}
__device__ __forceinline__ float tanh_approx(float x) {
  float r;
  asm("tanh.approx.f32 %0, %1;" : "=f"(r) : "f"(x));
  return r;
}
#define CPA_COMMIT() asm volatile("cp.async.commit_group;" ::: "memory")
#define CPA_WAIT(n)  asm volatile("cp.async.wait_group %0;" :: "n"(n) : "memory")

// ---------------- K1: h, e1, e2 ----------------
__global__ __launch_bounds__(256) void k1_h(const float* __restrict__ z,
    const float* __restrict__ W_in, const float* __restrict__ b_in,
    const float* __restrict__ w1, const float* __restrict__ w2) {
  int t = threadIdx.x;
  int sub = t >> 6;
  int j = t & 63;
  int bn = blockIdx.x * 4 + sub;
  __shared__ float W_s[64][65];
  __shared__ float zs[4][64];
  __shared__ float r1[4][64], r2[4][64];
  #pragma unroll
  for (int u = 0; u < 16; ++u) {
    int idx = t + 256*u;
    W_s[idx >> 6][idx & 63] = W_in[idx];
  }
  zs[sub][j] = z[bn*64 + j];
  __syncthreads();
  float acc = b_in[j];
  #pragma unroll
  for (int c = 0; c < 64; ++c) acc = fmaf(zs[sub][c], W_s[j][c], acc);
  float hv = fmaxf(acc, 0.0f);
  d_h[bn*64 + j] = hv;
  r1[sub][j] = hv * w1[j];
  r2[sub][j] = hv * w2[j];
  __syncthreads();
  if (j < 32) {
    float s1 = r1[sub][j] + r1[sub][j+32];
    float s2 = r2[sub][j] + r2[sub][j+32];
    #pragma unroll
    for (int o = 16; o > 0; o >>= 1) {
      s1 += __shfl_down_sync(0xffffffffu, s1, o);
      s2 += __shfl_down_sync(0xffffffffu, s2, o);
    }
    if (j == 0) { d_e1[bn] = s1; d_e2[bn] = s2; }
  }
}

// ---------------- K2: Ah = fp16 rowsoftmax(relu(emb emb^T)), padded ----------------
__global__ __launch_bounds__(256) void k2_A(const float* __restrict__ emb) {
  int n = blockIdx.x;
  int t = threadIdx.x;
  __shared__ float row[NN];
  __shared__ float e_n[16];
  __shared__ float red[256];
  if (t < 16) e_n[t] = emb[n*16 + t];
  __syncthreads();
  float lmax = -3e38f;
  for (int m = t; m < NN; m += 256) {
    const float* em = emb + m*16;
    float s = 0.f;
    #pragma unroll
    for (int d = 0; d < 16; ++d) s = fmaf(e_n[d], em[d], s);
    s = fmaxf(s, 0.f);
    row[m] = s;
    lmax = fmaxf(lmax, s);
  }
  red[t] = lmax; __syncthreads();
  for (int o = 128; o > 0; o >>= 1) {
    if (t < o) red[t] = fmaxf(red[t], red[t+o]);
    __syncthreads();
  }
  float mx = red[0];
  __syncthreads();
  float lsum = 0.f;
  for (int m = t; m < NN; m += 256) {
    float e = __expf(row[m] - mx);
    row[m] = e;
    lsum += e;
  }
  red[t] = lsum; __syncthreads();
  for (int o = 128; o > 0; o >>= 1) {
    if (t < o) red[t] += red[t+o];
    __syncthreads();
  }
  float inv = 1.0f / red[0];
  __syncthreads();
  for (int m = t; m < NN; m += 256) d_Ah[(size_t)n*NPAD + m] = __float2half(row[m] * inv);
  if (t < NPAD - NN) d_Ah[(size_t)n*NPAD + NN + t] = __float2half(0.f);
}

// ---------------- kv_pack_h: vT rows 0..63 = h^T, coalesced transpose ----------------
__global__ __launch_bounds__(256) void kv_pack_h() {
  int b  = blockIdx.y;
  int p0 = blockIdx.x * 128;
  int t = threadIdx.x;
  __shared__ float s[128][65];
  const float* Hb = d_h + (size_t)b*NN*64;
  #pragma unroll
  for (int u = 0; u < 32; ++u) {
    int idx = t + 256*u;
    int row = idx >> 6, col = idx & 63;
    int p = p0 + row;
    s[row][col] = (p < NN) ? Hb[(size_t)p*64 + col] : 0.f;
  }
  __syncthreads();
  __half* dst = d_vT + (size_t)b*VC*NPAD;
  #pragma unroll
  for (int u = 0; u < 16; ++u) {
    int idx = t + 256*u;
    int c = idx >> 6, q = idx & 63;
    int pl = q*2;
    __half2 v = __floats2half2_rn(s[pl][c], s[pl+1][c]);
    *(__half2*)(dst + (size_t)c*NPAD + p0 + pl) = v;
  }
}

// ---------------- kv_ones: vT row 128 = 1, rows 129..143 = 0 ----------------
__global__ __launch_bounds__(256) void kv_ones() {
  int b = blockIdx.x;
  int t = threadIdx.x;
  __half one = __float2half(1.f), zero = __float2half(0.f);
  __half* base = d_vT + (size_t)b*VC*NPAD;
  #pragma unroll
  for (int u = 0; u < 8; ++u) base[(size_t)128*NPAD + t + 256*u] = one;
  for (int c = 129; c < VC; ++c)
    #pragma unroll
    for (int u = 0; u < 8; ++u) base[(size_t)c*NPAD + t + 256*u] = zero;
}

// ---------------- K3: h2 = A @ h -> vT rows 64..127 ----------------
__global__ __launch_bounds__(256) void k3_mma() {
  int b  = blockIdx.y;
  int i0 = blockIdx.x * 128;
  int t = threadIdx.x;
  int w = t >> 5, lane = t & 31;
  int wm = w & 3, wn = w >> 2;
  int gid = lane >> 2, tid2 = lane & 3;

  __shared__ __half As[128*72];
  __shared__ __half Bs[64*72];

  const __half* Ag = d_Ah + (size_t)i0*NPAD;
  const __half* Bg = d_vT + (size_t)b*VC*NPAD;

  float acc[2][4][4];
  #pragma unroll
  for (int am = 0; am < 2; ++am)
    #pragma unroll
    for (int bn = 0; bn < 4; ++bn)
      #pragma unroll
      for (int r = 0; r < 4; ++r) acc[am][bn][r] = 0.f;

  #pragma unroll 1
  for (int k0 = 0; k0 < NPAD; k0 += 64) {
    __syncthreads();
    #pragma unroll
    for (int u = 0; u < 4; ++u) {
      int lin = t + 256*u;
      int row = lin >> 3, q = lin & 7;
      *(float4*)&As[row*72 + q*8] = *(const float4*)(Ag + (size_t)row*NPAD + k0 + q*8);
    }
    #pragma unroll
    for (int u = 0; u < 2; ++u) {
      int lin = t + 256*u;
      int row = lin >> 3, q = lin & 7;
      *(float4*)&Bs[row*72 + q*8] = *(const float4*)(Bg + (size_t)row*NPAD + k0 + q*8);
    }
    __syncthreads();
    #pragma unroll
    for (int kk = 0; kk < 4; ++kk) {
      int kb = kk*16;
      uint32_t a[2][4], bf[4][2];
      #pragma unroll
      for (int am = 0; am < 2; ++am) {
        int r0 = wm*32 + am*16 + gid;
        a[am][0] = *(const uint32_t*)&As[ r0      *72 + kb + tid2*2];
        a[am][1] = *(const uint32_t*)&As[(r0 + 8) *72 + kb + tid2*2];
        a[am][2] = *(const uint32_t*)&As[ r0      *72 + kb + tid2*2 + 8];
        a[am][3] = *(const uint32_t*)&As[(r0 + 8) *72 + kb + tid2*2 + 8];
      }
      #pragma unroll
      for (int bn = 0; bn < 4; ++bn) {
        int c0 = wn*32 + bn*8 + gid;
        bf[bn][0] = *(const uint32_t*)&Bs[c0*72 + kb + tid2*2];
        bf[bn][1] = *(const uint32_t*)&Bs[c0*72 + kb + tid2*2 + 8];
      }
      #pragma unroll
      for (int am = 0; am < 2; ++am)
        #pragma unroll
        for (int bn = 0; bn < 4; ++bn)
          mma16816(acc[am][bn], a[am][0], a[am][1], a[am][2], a[am][3], bf[bn][0], bf[bn][1]);
    }
  }

  __half* dst = d_vT + (size_t)b*VC*NPAD;
  int ib = i0 + wm*32 + gid;
  int cb = wn*32 + tid2*2;
  #pragma unroll
  for (int am = 0; am < 2; ++am) {
    #pragma unroll
    for (int bn = 0; bn < 4; ++bn) {
      int c = cb + bn*8;
      int i = ib + am*16;
      if (i < NN) {
        dst[(size_t)(64 + c    )*NPAD + i] = __float2half(acc[am][bn][0]);
        dst[(size_t)(64 + c + 1)*NPAD + i] = __float2half(acc[am][bn][1]);
      }
      if (i + 8 < NN) {
        dst[(size_t)(64 + c    )*NPAD + i + 8] = __float2half(acc[am][bn][2]);
        dst[(size_t)(64 + c + 1)*NPAD + i + 8] = __float2half(acc[am][bn][3]);
      }
    }
  }
}

// ---------------- kvs: vs -> fp16 padded ----------------
__global__ __launch_bounds__(256) void kvs_conv(const float* __restrict__ vs) {
  int idx = blockIdx.x * 256 + threadIdx.x;
  int row = idx >> 10, q = idx & 1023;
  int c0 = q * 2;
  float a = (row < NN && c0     < NN) ? vs[row*NN + c0]     : 0.f;
  float b = (row < NN && c0 + 1 < NN) ? vs[row*NN + c0 + 1] : 0.f;
  *(__half2*)(d_vsh + (size_t)row*NPAD + c0) = __floats2half2_rn(a, b);
}

// ---------------- kwo: W_out -> fp16 ----------------
__global__ __launch_bounds__(256) void kwo_conv(const float* __restrict__ W_out) {
  int idx = blockIdx.x * 256 + threadIdx.x;
  d_Woh[idx] = __float2half(W_out[idx]);
}

// ---------------- K4: sigT fp16 via h2exp/h2rcp ----------------
__global__ __launch_bounds__(256) void k4_sigT(const float* __restrict__ bs) {
  int b  = blockIdx.z;
  int m0 = blockIdx.y * 64;
  int p0 = blockIdx.x * 64;
  int t = threadIdx.x;
  __shared__ float s[64][65];
  #pragma unroll
  for (int u = 0; u < 16; ++u) {
    int idx = t + 256*u;
    int ml = idx >> 6, pl = idx & 63;
    int m = m0 + ml, p = p0 + pl;
    float x = 0.f;
    if (m < NN && p < NN)
      x = fmaf(d_e1[b*NN + m], d_e2[b*NN + p], bs[m*NN + p]);
    s[ml][pl] = fminf(fmaxf(x, -10.f), 10.f);
  }
  __syncthreads();
  __half* dst = d_sigT + (size_t)b*NPAD*NPAD;
  __half2 one2 = __float2half2_rn(1.f);
  #pragma unroll
  for (int u = 0; u < 8; ++u) {
    int idx = t + 256*u;
    int pl = idx >> 5, m2 = idx & 31;
    __half2 hx = __floats2half2_rn(s[m2*2][pl], s[m2*2+1][pl]);
    __half2 sig = h2rcp(__hadd2(one2, h2exp(__hneg2(hx))));
    *(__half2*)(dst + (size_t)(p0+pl)*NPAD + m0 + m2*2) = sig;
  }
}

// ---------------- K5a: expT = exp(vs @ sig) -- 128x128 tile, 2 CTAs/SM, manual frags (round-14) ----------------
__global__ __launch_bounds__(256, 2) void k5a_mma() {
  extern __shared__ __half dsm[];
  int b  = blockIdx.z;
  int i0 = blockIdx.y * 128;
  int j0 = blockIdx.x * 128;
  int t = threadIdx.x;
  int w = t >> 5, lane = t & 31;
  int wm = w & 1, wn = w >> 1;
  int gid = lane >> 2, tid2 = lane & 3;

  const int BUF = 256*72;
  uint32_t sbase = smem_u32(dsm);

  const __half* Ag = d_vsh  + (size_t)i0 * NPAD;
  const __half* Bg = d_sigT + ((size_t)b * NPAD + j0) * NPAD;

  auto issue = [&](int buf, int k0) {
    uint32_t ab = sbase + (uint32_t)buf*BUF*2u;
    uint32_t bb = ab + 128u*72u*2u;
    #pragma unroll
    for (int u = 0; u < 4; ++u) {
      int lin = t + 256*u;
      int row = lin >> 3, q = lin & 7;
      cpa16(ab + (uint32_t)(row*72 + q*8)*2u, Ag + (size_t)row*NPAD + k0 + q*8);
      cpa16(bb + (uint32_t)(row*72 + q*8)*2u, Bg + (size_t)row*NPAD + k0 + q*8);
    }
    CPA_COMMIT();
  };

  float acc[4][4][4];
  #pragma unroll
  for (int am = 0; am < 4; ++am)
    #pragma unroll
    for (int bn = 0; bn < 4; ++bn)
      #pragma unroll
      for (int r = 0; r < 4; ++r) acc[am][bn][r] = 0.f;

  issue(0, 0);

  #pragma unroll 1
  for (int kt = 0; kt < NPAD/64; ++kt) {
    int cur = kt & 1;
    CPA_WAIT(0);
    __syncthreads();
    if (kt + 1 < NPAD/64) issue(cur ^ 1, (kt + 1)*64);
    const __half* Asc = dsm + cur*BUF;
    const __half* Bsc = Asc + 128*72;
    #pragma unroll
    for (int kk = 0; kk < 4; ++kk) {
      int kb = kk*16;
      uint32_t a[4][4];
      #pragma unroll
      for (int am = 0; am < 4; ++am) {
        int r0 = wm*64 + am*16 + gid;
        a[am][0] = *(const uint32_t*)&Asc[ r0      *72 + kb + tid2*2];
        a[am][1] = *(const uint32_t*)&Asc[(r0 + 8) *72 + kb + tid2*2];
        a[am][2] = *(const uint32_t*)&Asc[ r0      *72 + kb + tid2*2 + 8];
        a[am][3] = *(const uint32_t*)&Asc[(r0 + 8) *72 + kb + tid2*2 + 8];
      }
      #pragma unroll
      for (int bn = 0; bn < 4; ++bn) {
        int c0 = wn*32 + bn*8 + gid;
        uint32_t bf0 = *(const uint32_t*)&Bsc[c0*72 + kb + tid2*2];
        uint32_t bf1 = *(const uint32_t*)&Bsc[c0*72 + kb + tid2*2 + 8];
        #pragma unroll
        for (int am = 0; am < 4; ++am)
          mma16816(acc[am][bn], a[am][0], a[am][1], a[am][2], a[am][3], bf0, bf1);
      }
    }
  }

  // epilogue: exp(fp16) -> smem staging [128][136] -> coalesced write
  __syncthreads();
  __half* sH = dsm;
  const int SST = 136;
  #pragma unroll
  for (int am = 0; am < 4; ++am) {
    #pragma unroll
    for (int bn = 0; bn < 4; ++bn) {
      int lr = wm*64 + am*16 + gid;
      int lc = wn*32 + bn*8 + tid2*2;
      __half2 t0 = __floats2half2_rn(fminf(acc[am][bn][0], 11.f), fminf(acc[am][bn][1], 11.f));
      __half2 t1 = __floats2half2_rn(fminf(acc[am][bn][2], 11.f), fminf(acc[am][bn][3], 11.f));
      *(__half2*)&sH[ lr      *SST + lc] = h2exp(t0);
      *(__half2*)&sH[(lr + 8) *SST + lc] = h2exp(t1);
    }
  }
  __syncthreads();
  __half2 zz = __floats2half2_rn(0.f, 0.f);
  #pragma unroll
  for (int u = 0; u < 32; ++u) {
    int idx = t + 256*u;
    int row = idx >> 6, q = idx & 63;
    int i = i0 + row, j = j0 + q*2;
    if (i < NN) {
      __half2 v = (j < NN) ? *(__half2*)&sH[row*SST + q*2] : zz;
      *(__half2*)(d_expT + ((size_t)b*NPAD + i)*NPAD + j) = v;
    }
  }
}

// ---------------- K5b: xg_raw = expT @ vT^T ----------------
__global__ __launch_bounds__(256) void k5b_mma() {
  int b  = blockIdx.y;
  int i0 = blockIdx.x * 64;
  int t = threadIdx.x;
  int w = t >> 5, lane = t & 31;
  int wm = w & 3, wn = w >> 2;
  int gid = lane >> 2, tid2 = lane & 3;

  __shared__ __half As[64*72];
  __shared__ __half Bs[VC*72];

  const __half* Ag = d_expT + ((size_t)b*NPAD + i0)*NPAD;
  const __half* Bg = d_vT + (size_t)b*VC*NPAD;

  float acc[9][4];
  #pragma unroll
  for (int bn = 0; bn < 9; ++bn)
    #pragma unroll
    for (int r = 0; r < 4; ++r) acc[bn][r] = 0.f;

  #pragma unroll 1
  for (int k0 = 0; k0 < NPAD; k0 += 64) {
    __syncthreads();
    #pragma unroll
    for (int u = 0; u < 2; ++u) {
      int lin = t + 256*u;
      int row = lin >> 3, q = lin & 7;
      *(float4*)&As[row*72 + q*8] = *(const float4*)(Ag + (size_t)row*NPAD + k0 + q*8);
    }
    #pragma unroll
    for (int u = 0; u < 5; ++u) {
      int lin = t + 256*u;
      if (lin < VC*8) {
        int row = lin >> 3, q = lin & 7;
        *(float4*)&Bs[row*72 + q*8] = *(const float4*)(Bg + (size_t)row*NPAD + k0 + q*8);
      }
    }
    __syncthreads();
    #pragma unroll
    for (int kk = 0; kk < 4; ++kk) {
      int kb = kk*16;
      int r0 = wm*16 + gid;
      uint32_t a0 = *(const uint32_t*)&As[ r0      *72 + kb + tid2*2];
      uint32_t a1 = *(const uint32_t*)&As[(r0 + 8) *72 + kb + tid2*2];
      uint32_t a2 = *(const uint32_t*)&As[ r0      *72 + kb + tid2*2 + 8];
      uint32_t a3 = *(const uint32_t*)&As[(r0 + 8) *72 + kb + tid2*2 + 8];
      #pragma unroll
      for (int bn = 0; bn < 9; ++bn) {
        int c0 = wn*72 + bn*8 + gid;
        uint32_t bf0 = *(const uint32_t*)&Bs[c0*72 + kb + tid2*2];
        uint32_t bf1 = *(const uint32_t*)&Bs[c0*72 + kb + tid2*2 + 8];
        mma16816(acc[bn], a0, a1, a2, a3, bf0, bf1);
      }
    }
  }

  int i = i0 + wm*16 + gid;
  #pragma unroll
  for (int bn = 0; bn < 9; ++bn) {
    int c = wn*72 + bn*8 + tid2*2;
    if (c < 128) {
      if (i < NN)
        *(float2*)&d_xg[((size_t)b*NN + i)*128 + c]     = make_float2(acc[bn][0], acc[bn][1]);
      if (i + 8 < NN)
        *(float2*)&d_xg[((size_t)b*NN + i + 8)*128 + c] = make_float2(acc[bn][2], acc[bn][3]);
    } else if (c == 128) {
      if (i < NN)     d_rs[b*NN + i]     = acc[bn][0];
      if (i + 8 < NN) d_rs[b*NN + i + 8] = acc[bn][2];
    }
  }
}

// ---------------- kw: w_allh = emb @ wp (fp16 out) ----------------
__global__ __launch_bounds__(256) void kw(const float* __restrict__ emb,
                                          const float* __restrict__ wp) {
  int c0 = blockIdx.x * 512;
  int n0 = blockIdx.y * 32;
  int t = threadIdx.x;
  __shared__ float wp_s[16][512];
  __shared__ float e_s[32][17];
  #pragma unroll
  for (int u = 0; u < 32; ++u) {
    int idx = t + 256*u;
    int d = idx >> 9, col = idx & 511;
    wp_s[d][col] = wp[d*8192 + c0 + col];
  }
  #pragma unroll
  for (int u = 0; u < 2; ++u) {
    int idx = t + 256*u;
    int nl = idx >> 4, d = idx & 15;
    e_s[nl][d] = (n0 + nl < NN) ? emb[(n0+nl)*16 + d] : 0.f;
  }
  __syncthreads();
  #pragma unroll 4
  for (int u = 0; u < 32; ++u) {
    int idx = t + 256*u;
    int nl = idx >> 8, cp = idx & 255;
    int col = cp*2;
    float a0 = 0.f, a1 = 0.f;
    #pragma unroll
    for (int d = 0; d < 16; ++d) {
      float e = e_s[nl][d];
      a0 = fmaf(e, wp_s[d][col],     a0);
      a1 = fmaf(e, wp_s[d][col + 1], a1);
    }
    if (n0 + nl < NN)
      *(__half2*)&d_wallh[(size_t)(n0+nl)*8192 + c0 + col] = __floats2half2_rn(a0, a1);
  }
}

// ---------------- K6: g(fp16) = bias + (xg_raw @ w_all[n]) / rowsum ----------------
__global__ __launch_bounds__(256) void k6_g(const float* __restrict__ emb,
                                            const float* __restrict__ bp) {
  int n = blockIdx.x;
  int t = threadIdx.x;
  __shared__ float w_s[8192];
  __shared__ float e_s[16];
  __shared__ float bias_s[64];
  __shared__ float xg_s[8][128];
  __shared__ float inv_s[8];
  if (t < 16) e_s[t] = emb[n*16 + t];
  if (t >= 32 && t < 40) inv_s[t-32] = 1.0f / d_rs[(t-32)*NN + n];
  __syncthreads();
  #pragma unroll 4
  for (int u = 0; u < 16; ++u) {
    int idx = t + 256*u;
    __half2 hv = *(const __half2*)&d_wallh[(size_t)n*8192 + idx*2];
    float2 fv = __half22float2(hv);
    w_s[idx*2]     = fv.x;
    w_s[idx*2 + 1] = fv.y;
  }
  if (t < 64) {
    float acc = 0.f;
    #pragma unroll
    for (int d = 0; d < 16; ++d) acc = fmaf(e_s[d], bp[d*64 + t], acc);
    bias_s[t] = acc;
  }
  #pragma unroll
  for (int u = 0; u < 4; ++u) {
    int idx = t + 256*u;
    int b = idx >> 7, ki = idx & 127;
    xg_s[b][ki] = d_xg[((size_t)b*NN + n)*128 + ki];
  }
  __syncthreads();
  #pragma unroll
  for (int u = 0; u < 2; ++u) {
    int idx = t + 256*u;
    int b = idx >> 6, o = idx & 63;
    float acc = 0.f;
    #pragma unroll 8
    for (int ki = 0; ki < 128; ++ki) acc = fmaf(xg_s[b][ki], w_s[ki*64 + o], acc);
    d_gh[(b*NN + n)*64 + o] = __float2half(fmaf(acc, inv_s[b], bias_s[o]));
  }
}

// ---------------- K7: out = 0.1*tanh(g @ W_out^T + b_out) via HMMA + MUFU.TANH ----------------
__global__ __launch_bounds__(256) void k7_mma(const float* __restrict__ b_out,
                                              float* __restrict__ out) {
  int o0 = blockIdx.x * 128;
  int r0g = blockIdx.y * 128;
  int t = threadIdx.x;
  int w = t >> 5, lane = t & 31;
  int wm = w & 1, wn = w >> 1;
  int gid = lane >> 2, tid2 = lane & 3;

  __shared__ __half As[128*72];
  __shared__ __half Bs[128*72];

  #pragma unroll
  for (int u = 0; u < 4; ++u) {
    int lin = t + 256*u;
    int row = lin >> 3, q = lin & 7;
    *(float4*)&As[row*72 + q*8] = *(const float4*)(d_gh  + (size_t)(r0g + row)*64 + q*8);
    *(float4*)&Bs[row*72 + q*8] = *(const float4*)(d_Woh + (size_t)(o0  + row)*64 + q*8);
  }
  __syncthreads();

  float acc[4][4][4];
  #pragma unroll
  for (int am = 0; am < 4; ++am)
    #pragma unroll
    for (int bn = 0; bn < 4; ++bn)
      #pragma unroll
      for (int r = 0; r < 4; ++r) acc[am][bn][r] = 0.f;

  #pragma unroll
  for (int kk = 0; kk < 4; ++kk) {
    int kb = kk*16;
    uint32_t a[4][4];
    #pragma unroll
    for (int am = 0; am < 4; ++am) {
      int r0 = wm*64 + am*16 + gid;
      a[am][0] = *(const uint32_t*)&As[ r0      *72 + kb + tid2*2];
      a[am][1] = *(const uint32_t*)&As[(r0 + 8) *72 + kb + tid2*2];
      a[am][2] = *(const uint32_t*)&As[ r0      *72 + kb + tid2*2 + 8];
      a[am][3] = *(const uint32_t*)&As[(r0 + 8) *72 + kb + tid2*2 + 8];
    }
    #pragma unroll
    for (int bn = 0; bn < 4; ++bn) {
      int c0 = wn*32 + bn*8 + gid;
      uint32_t bf0 = *(const uint32_t*)&Bs[c0*72 + kb + tid2*2];
      uint32_t bf1 = *(const uint32_t*)&Bs[c0*72 + kb + tid2*2 + 8];
      #pragma unroll
      for (int am = 0; am < 4; ++am)
        mma16816(acc[am][bn], a[am][0], a[am][1], a[am][2], a[am][3], bf0, bf1);
    }
  }

  #pragma unroll
  for (int bn = 0; bn < 4; ++bn) {
    int j = o0 + wn*32 + bn*8 + tid2*2;
    float2 bo = *(const float2*)&b_out[j];
    #pragma unroll
    for (int am = 0; am < 4; ++am) {
      int i = r0g + wm*64 + am*16 + gid;
      float2 v0, v1;
      v0.x = 0.1f * tanh_approx(acc[am][bn][0] + bo.x);
      v0.y = 0.1f * tanh_approx(acc[am][bn][1] + bo.y);
      v1.x = 0.1f * tanh_approx(acc[am][bn][2] + bo.x);
      v1.y = 0.1f * tanh_approx(acc[am][bn][3] + bo.y);
      *(float2*)&out[(size_t)i*4096 + j]       = v0;
      *(float2*)&out[(size_t)(i+8)*4096 + j]   = v1;
    }
  }
}

// ---------------- launch ----------------
extern "C" void kernel_launch(void* const* d_in, const int* in_sizes, int n_in,
                              void* d_out, int out_size) {
  const float* z     = (const float*)d_in[0];
  const float* W_in  = (const float*)d_in[1];
  const float* b_in  = (const float*)d_in[2];
  const float* W_out = (const float*)d_in[3];
  const float* b_out = (const float*)d_in[4];
  const float* emb   = (const float*)d_in[5];
  const float* wp    = (const float*)d_in[6];
  const float* bp    = (const float*)d_in[7];
  const float* w1    = (const float*)d_in[8];
  const float* w2    = (const float*)d_in[9];
  const float* vs    = (const float*)d_in[10];
  const float* bs    = (const float*)d_in[11];
  float* out = (float*)d_out;

  static bool attr_set = false;
  if (!attr_set) {
    cudaFuncSetAttribute(k5a_mma, cudaFuncAttributeMaxDynamicSharedMemorySize, 73728);
    attr_set = true;
  }

  // k4_sigT placed 4th so the ncu window captures it this round.
  k1_h<<<4000, 256>>>(z, W_in, b_in, w1, w2);
  kvs_conv<<<8192, 256>>>(vs);
  kwo_conv<<<1024, 256>>>(W_out);
  k4_sigT<<<dim3(32, 32, NB), 256>>>(bs);
  k5a_mma<<<dim3(16, 16, NB), 256, 73728>>>();
  k2_A<<<NN, 256>>>(emb);
  kv_pack_h<<<dim3(16, NB), 256>>>();
  kv_ones<<<NB, 256>>>();
  k3_mma<<<dim3(16, NB), 256>>>();
  k5b_mma<<<dim3(32, NB), 256>>>();
  kw<<<dim3(16, 63), 256>>>(emb, wp);
  k6_g<<<NN, 256>>>(emb, bp);
  k7_mma<<<dim3(32, 125), 256>>>(b_out, out);
}